// round 9
// baseline (speedup 1.0000x reference)
#include <cuda_runtime.h>

// Problem constants
#define BB 16
#define GG 32
#define TT 180
#define NN 1024   // H*W
#define FF 1024
#define SCALE 0.04419417382415922f  // 512^-0.5
#define EPSF 1e-6f
#define WPART 32  // weight-reduction blocks

// ---------------- scratch (no allocs allowed) ----------------
__device__ __align__(16) float g_part[WPART * 512];   // partial column sums of wq
__device__ __align__(16) float g_wa[512];             // wqs[c]*gamma[c]
__device__ __align__(16) float g_Wsum[512];           // row sums of wo
__device__ float g_const1;                            // sum(wqs*beta) + sum(bq)
__device__ float g_sum[BB * GG];
__device__ float g_sq[BB * GG];
__device__ float g_rs[BB * GG];
__device__ float g_d[BB];
__device__ __align__(16) float g_k[BB * FF];
__device__ __align__(16) float g_v[BB * FF];
__device__ __align__(16) float g_A[BB * NN];
__device__ int g_c1 = 0;      // kA last-block ticket

// ---------------- kA: stats ∥ k/v GEMM ∥ weight reductions (all independent) ----------
// grid 608, block 512.
//   bid [0,512):    per-(b,g) x stats (8 channels per thread).
//   bid [512,576):  k/v GEMM, 32-f x 16-b tiles.
//   bid [576,608):  wq column-partials (16 rows/block) + wo row-sums (1 row/warp).
// Last arriving block finalizes: wqs -> wa/const1/wg(smem), then rs/d.
__global__ void __launch_bounds__(512) kA(
    const float* __restrict__ x, const float* __restrict__ cond,
    const float* __restrict__ gamma, const float* __restrict__ beta,
    const float* __restrict__ wq, const float* __restrict__ bq,
    const float* __restrict__ wk, const float* __restrict__ bk,
    const float* __restrict__ wv, const float* __restrict__ bv,
    const float* __restrict__ wo)
{
    __shared__ float smem[48 * 181 + 64];   // 35KB (k3: sw[32][181]+sc[16][181])
    int t = threadIdx.x;
    int bid = blockIdx.x;
    int w = t >> 5, lane = t & 31;

    if (bid < 512) {
        // ---- x stats for (b,g) = bid: thread handles 8 channels at float4 col f4 ----
        const float4* xs = (const float4*)x + (size_t)bid * 16 * 256;
        int f4 = t & 255, cg = t >> 8;   // cg in {0,1}
        float sum = 0.f, sq = 0.f;
#pragma unroll
        for (int c = 0; c < 8; c++) {
            float4 v = xs[(cg * 8 + c) * 256 + f4];
            sum += v.x + v.y + v.z + v.w;
            sq += v.x * v.x + v.y * v.y + v.z * v.z + v.w * v.w;
        }
        float* s1 = smem;
        float* s2 = smem + 512;
        s1[t] = sum; s2[t] = sq;
        __syncthreads();
        for (int st = 256; st; st >>= 1) {
            if (t < st) { s1[t] += s1[t + st]; s2[t] += s2[t + st]; }
            __syncthreads();
        }
        if (t == 0) { g_sum[bid] = s1[0]; g_sq[bid] = s2[0]; }
    } else if (bid < 576) {
        // ---- k/v GEMM: 32 f x 16 b per block ----
        int bx = bid - 512;               // 0..63
        int mat = bx >> 5;                // 0 = k, 1 = v
        int ft = bx & 31;                 // f-tile of 32
        const float* W    = mat ? wv : wk;
        const float* bias = mat ? bv : bk;
        float* o          = mat ? g_v : g_k;

        float (*sw)[181] = (float (*)[181])smem;               // [32][181]
        float (*sc)[181] = (float (*)[181])(smem + 32 * 181);  // [16][181]
        int f0 = ft * 32;
        for (int i = t; i < 32 * 180; i += 512) {
            int r = i / 180, cc2 = i - r * 180;
            sw[r][cc2] = W[(size_t)(f0 + r) * TT + cc2];
        }
        for (int i = t; i < 16 * 180; i += 512) {
            int r = i / 180, cc2 = i - r * 180;
            sc[r][cc2] = cond[r * TT + cc2];
        }
        __syncthreads();

        int fo = t & 31, bb = t >> 5;
        float acc = 0.f;
#pragma unroll 4
        for (int k = 0; k < TT; k++) acc += sw[fo][k] * sc[bb][k];
        o[bb * FF + f0 + fo] = acc + bias[f0 + fo];
    } else {
        // ---- weight reductions: block j owns 16 rows of wq and wo ----
        int j = bid - 576;                // 0..31
        float s0 = 0.f;
#pragma unroll
        for (int r = 0; r < 16; r++) s0 += wq[(size_t)(j * 16 + r) * 512 + t];
        g_part[j * 512 + t] = s0;

        // wo row sum: warp w owns row j*16+w
        const float* rp = wo + (size_t)(j * 16 + w) * 512;
        float r = 0.f;
#pragma unroll
        for (int i = 0; i < 16; i++) r += rp[lane + 32 * i];
#pragma unroll
        for (int off = 16; off; off >>= 1) r += __shfl_down_sync(0xffffffffu, r, off);
        if (lane == 0) g_Wsum[j * 16 + w] = r;
    }

    // ---- last-block election over all 608 blocks (no spin) ----
    __syncthreads();
    __threadfence();
    __shared__ int isLast;
    if (t == 0) isLast = (atomicAdd(&g_c1, 1) == 607);
    __syncthreads();
    if (!isLast) return;
    __threadfence();

    // ---- finalize weights: wqs -> wa, const1, wg (smem) ----
    float wqs = 0.f;
#pragma unroll 8
    for (int jj = 0; jj < WPART; jj++) wqs += g_part[jj * 512 + t];
    float wa = wqs * gamma[t];
    g_wa[t] = wa;

    float* swg = smem + 1024;   // 32 floats
    smem[t] = wqs * beta[t] + bq[t];
    __syncthreads();
    for (int st = 256; st; st >>= 1) {
        if (t < st) smem[t] += smem[t + st];
        __syncthreads();
    }
    if (t == 0) { g_const1 = smem[0]; g_c1 = 0; }  // reset ticket for replay

    // per-group (16-ch) sums of wa -> swg (group = t>>4, exactly 32 groups)
    float wg = wa;
#pragma unroll
    for (int off = 8; off; off >>= 1) wg += __shfl_down_sync(0xffffffffu, wg, off, 16);
    if ((t & 15) == 0) swg[t >> 4] = wg;
    __syncthreads();

    // ---- rs for all 512 (b,g); d[b] per batch (one warp per batch) ----
    float* tmp = smem + 1088;
    const float inv = 1.f / 16384.f;
    {
        float mean = g_sum[t] * inv;
        float var = g_sq[t] * inv - mean * mean;
        float rs = rsqrtf(var + EPSF);
        g_rs[t] = rs;
        tmp[t] = mean * rs * swg[t & 31];
    }
    __syncthreads();
    float c1 = g_const1;
    {
        float v = tmp[w * 32 + lane];
#pragma unroll
        for (int off = 16; off; off >>= 1) v += __shfl_down_sync(0xffffffffu, v, off);
        if (lane == 0) g_d[w] = c1 - v;
    }
}

// ---------------- kC: S from x + softmax-weighted average -> g_A ----------------
// grid 256 (b = blk>>4, 64-n chunk = blk&15), block 512 (16 warps).
__global__ void __launch_bounds__(512) kC(const float* __restrict__ x)
{
    __shared__ float sk[1024], sv[1024], wch[512], part[512], sS[64];
    int bid = blockIdx.x;
    int b  = bid >> 4;
    int nc = bid & 15;
    int n0 = nc * 64;
    int t = threadIdx.x;
    int w = t >> 5, lane = t & 31;

    if (t < 256) ((float4*)sk)[t] = ((const float4*)(g_k + b * FF))[t];
    else         ((float4*)sv)[t - 256] = ((const float4*)(g_v + b * FF))[t - 256];
    wch[t] = g_rs[b * 32 + (t >> 4)] * g_wa[t];
    float d = g_d[b];
    __syncthreads();

    // ---- Phase S: thread t handles n = t&63, channel group cg = t>>6 (64 chans) ----
    {
        int n = t & 63, cg = t >> 6;
        const float* xb = x + ((size_t)b * 512 + cg * 64) * 1024 + n0 + n;
        float acc = 0.f;
#pragma unroll 16
        for (int k = 0; k < 64; k++) acc += wch[cg * 64 + k] * xb[(size_t)k * 1024];
        part[t] = acc;
    }
    __syncthreads();
    if (t < 64) {
        float s = 0.f;
#pragma unroll
        for (int j = 0; j < 8; j++) s += part[t + 64 * j];
        sS[t] = (s + d) * SCALE;
    }
    __syncthreads();

    // ---- softmax-weighted average (no max-sub: logits tiny by construction) ----
#pragma unroll
    for (int i = 0; i < 4; i++) {
        int n = w * 4 + i;
        float s = sS[n];
        float l = 0.f, acc = 0.f;
#pragma unroll
        for (int j = 0; j < 8; j++) {
            float4 k4v = ((float4*)sk)[j * 32 + lane];
            float4 v4  = ((float4*)sv)[j * 32 + lane];
            float e0 = __expf(s * k4v.x), e1 = __expf(s * k4v.y);
            float e2 = __expf(s * k4v.z), e3 = __expf(s * k4v.w);
            l += e0 + e1 + e2 + e3;
            acc += v4.x * e0 + v4.y * e1 + v4.z * e2 + v4.w * e3;
        }
#pragma unroll
        for (int off = 16; off; off >>= 1) {
            l   += __shfl_xor_sync(0xffffffffu, l, off);
            acc += __shfl_xor_sync(0xffffffffu, acc, off);
        }
        if (lane == 0) g_A[b * NN + n0 + n] = acc / l;
    }
}

// ---------------- kD: out = x + Wsum[c]*A[b,n] + bo[c], pure linear stream -------
// float4 over n. 8192 blocks x 256.
__global__ void __launch_bounds__(256) kD(
    const float* __restrict__ x, const float* __restrict__ bo,
    float* __restrict__ out)
{
    size_t i = (size_t)blockIdx.x * 256 + threadIdx.x;  // float4 index
    int n4 = (int)(i & 255);
    int c = (int)((i >> 8) & 511);
    int b = (int)(i >> 17);
    float4 xv = ((const float4*)x)[i];
    float4 av = ((const float4*)g_A)[b * 256 + n4];
    float wv = g_Wsum[c];
    float bb = bo[c];
    float4 o;
    o.x = xv.x + wv * av.x + bb;
    o.y = xv.y + wv * av.y + bb;
    o.z = xv.z + wv * av.z + bb;
    o.w = xv.w + wv * av.w + bb;
    ((float4*)out)[i] = o;
}

extern "C" void kernel_launch(void* const* d_in, const int* in_sizes, int n_in,
                              void* d_out, int out_size) {
    const float* x     = (const float*)d_in[0];
    const float* cond  = (const float*)d_in[1];
    const float* gamma = (const float*)d_in[2];
    const float* beta  = (const float*)d_in[3];
    const float* wq    = (const float*)d_in[4];
    const float* bq    = (const float*)d_in[5];
    const float* wk    = (const float*)d_in[6];
    const float* bk    = (const float*)d_in[7];
    const float* wv    = (const float*)d_in[8];
    const float* bv    = (const float*)d_in[9];
    const float* wo    = (const float*)d_in[10];
    const float* bo    = (const float*)d_in[11];
    float* out = (float*)d_out;

    kA<<<608, 512>>>(x, cond, gamma, beta, wq, bq, wk, bk, wv, bv, wo);
    kC<<<256, 512>>>(x);
    kD<<<8192, 256>>>(x, bo, out);
}